// round 5
// baseline (speedup 1.0000x reference)
#include <cuda_runtime.h>
#include <cstdint>
#include <cstddef>

// ---------------- static problem shape ----------------
constexpr int BSZ = 2;
constexpr int NQ  = 21760;
constexpr int MR  = BSZ * NQ;      // 43520 rows
constexpr int D   = 256;
constexpr int NH  = 8;
constexpr int DH  = 32;
constexpr int NFUSED = 384;        // 256 offs + 128 attn logits

__device__ __constant__ int c_LW[4] = {128, 64, 32, 16};
__device__ __constant__ int c_LH[4] = {128, 64, 32, 16};
__device__ __constant__ int c_LS[4] = {0, 16384, 20480, 21504};

// ---------------- scratch ----------------
__device__ float  g_vt[(size_t)BSZ * NH * NQ * DH];     // v transposed: [b][h][pos][c]
__device__ float  g_P [(size_t)MR * NFUSED];            // raw offs(256) + attn logits(128)
__device__ float  g_tmp[(size_t)MR * D];                // attention output before Wout
__device__ float  g_Wf[D * NFUSED];                     // fused [Wo | Wa]
__device__ float  g_bf[NFUSED];                         // fused [bo | ba]

// ---------------- helpers ----------------
__device__ __forceinline__ void mma_tf32(float& c0, float& c1, float& c2, float& c3,
                                         uint32_t a0, uint32_t a1, uint32_t a2, uint32_t a3,
                                         uint32_t b0, uint32_t b1) {
    asm volatile(
        "mma.sync.aligned.m16n8k8.row.col.f32.tf32.tf32.f32 "
        "{%0,%1,%2,%3}, {%4,%5,%6,%7}, {%8,%9}, {%0,%1,%2,%3};"
        : "+f"(c0), "+f"(c1), "+f"(c2), "+f"(c3)
        : "r"(a0), "r"(a1), "r"(a2), "r"(a3), "r"(b0), "r"(b1));
}

__device__ __forceinline__ void cp16(void* smem_dst, const void* gsrc) {
    unsigned d = (unsigned)__cvta_generic_to_shared(smem_dst);
    asm volatile("cp.async.cg.shared.global [%0], [%1], 16;" :: "r"(d), "l"(gsrc));
}

// ---------------- pack fused weight ----------------
__global__ void pack_w_kernel(const float* __restrict__ Wo, const float* __restrict__ bo,
                              const float* __restrict__ Wa, const float* __restrict__ ba) {
    int i = blockIdx.x * blockDim.x + threadIdx.x;
    if (i < D * NFUSED) {
        int k = i / NFUSED, n = i % NFUSED;
        g_Wf[i] = (n < 256) ? Wo[k * 256 + n] : Wa[k * 128 + (n - 256)];
    }
    if (i < NFUSED) g_bf[i] = (i < 256) ? bo[i] : ba[i - 256];
}

// ---------------- tf32 tensor-core GEMM, cp.async double-buffered ----------------
// Tile: BM=128, BN=128, BK=16.  8 warps as 4(M) x 2(N), warp tile 32x64.
// Raw fp32 bits fed to mma.tf32 (HW truncates mantissa; no cvt in hot loop).
// MODE 0: A=value, W=Wv   -> scatter into g_vt [b][h][pos][c]
// MODE 1: A=query, W=g_Wf -> g_P row-major
// MODE 2: A=g_tmp, W=Wout -> Cout = acc + bias + addin (residual)
template<int MODE>
__global__ __launch_bounds__(256)
void gemm_tc(const float* __restrict__ Ain, const float* __restrict__ Win,
             const float* __restrict__ biasin, const float* __restrict__ addin,
             float* __restrict__ Cout, int N)
{
    constexpr int K = D;
    const float* A    = (MODE == 2) ? g_tmp : Ain;
    const float* W    = (MODE == 1) ? g_Wf  : Win;
    const float* bias = (MODE == 1) ? g_bf  : biasin;

    __shared__ float As[2][128][20];    // [buf][m][k], stride 20 -> conflict-free
    __shared__ float Bs[2][16][136];    // [buf][k][n], stride 136 -> conflict-free

    const int tid  = threadIdx.x;
    const int warp = tid >> 5;
    const int lane = tid & 31;
    const int wm   = (warp & 3) * 32;
    const int wn   = (warp >> 2) * 64;
    const int m0   = blockIdx.x * 128;
    const int n0   = blockIdx.y * 128;

    const int ar = tid >> 2;   // 0..63 (and +64)
    const int aq = tid & 3;
    const int br = tid >> 4;   // 0..15
    const int bc = tid & 15;

    float c[2][8][4];
    #pragma unroll
    for (int mf = 0; mf < 2; ++mf)
        #pragma unroll
        for (int nf = 0; nf < 8; ++nf)
            #pragma unroll
            for (int i = 0; i < 4; ++i) c[mf][nf][i] = 0.f;

    auto load_stage = [&](int kt, int buf) {
        const int kk = kt * 16;
        cp16(&As[buf][ar][aq * 4],      A + (size_t)(m0 + ar) * K + kk + aq * 4);
        cp16(&As[buf][ar + 64][aq * 4], A + (size_t)(m0 + ar + 64) * K + kk + aq * 4);
        cp16(&Bs[buf][br][bc * 4],        W + (size_t)(kk + br) * N + n0 + bc * 4);
        cp16(&Bs[buf][br][(bc + 16) * 4], W + (size_t)(kk + br) * N + n0 + (bc + 16) * 4);
        asm volatile("cp.async.commit_group;" ::: "memory");
    };

    load_stage(0, 0);

    for (int kt = 0; kt < 16; ++kt) {
        const int buf = kt & 1;
        if (kt + 1 < 16) {
            load_stage(kt + 1, buf ^ 1);
            asm volatile("cp.async.wait_group 1;" ::: "memory");
        } else {
            asm volatile("cp.async.wait_group 0;" ::: "memory");
        }
        __syncthreads();

        #pragma unroll
        for (int kc = 0; kc < 16; kc += 8) {
            uint32_t a[2][4], b[8][2];
            const int arow = wm + (lane >> 2);
            const int acol = kc + (lane & 3);
            #pragma unroll
            for (int mf = 0; mf < 2; ++mf) {
                const int r0 = arow + mf * 16;
                a[mf][0] = __float_as_uint(As[buf][r0    ][acol    ]);
                a[mf][1] = __float_as_uint(As[buf][r0 + 8][acol    ]);
                a[mf][2] = __float_as_uint(As[buf][r0    ][acol + 4]);
                a[mf][3] = __float_as_uint(As[buf][r0 + 8][acol + 4]);
            }
            #pragma unroll
            for (int nf = 0; nf < 8; ++nf) {
                const int nn = wn + nf * 8 + (lane >> 2);
                b[nf][0] = __float_as_uint(Bs[buf][acol    ][nn]);
                b[nf][1] = __float_as_uint(Bs[buf][acol + 4][nn]);
            }
            #pragma unroll
            for (int mf = 0; mf < 2; ++mf)
                #pragma unroll
                for (int nf = 0; nf < 8; ++nf)
                    mma_tf32(c[mf][nf][0], c[mf][nf][1], c[mf][nf][2], c[mf][nf][3],
                             a[mf][0], a[mf][1], a[mf][2], a[mf][3],
                             b[nf][0], b[nf][1]);
        }
        __syncthreads();
    }

    // epilogue
    #pragma unroll
    for (int mf = 0; mf < 2; ++mf) {
        #pragma unroll
        for (int nf = 0; nf < 8; ++nf) {
            const int cb = n0 + wn + nf * 8 + 2 * (lane & 3);
            const float2 b2 = *reinterpret_cast<const float2*>(bias + cb);
            #pragma unroll
            for (int half = 0; half < 2; ++half) {
                const int row = m0 + wm + mf * 16 + (lane >> 2) + half * 8;
                const float v0 = c[mf][nf][half * 2 + 0] + b2.x;
                const float v1 = c[mf][nf][half * 2 + 1] + b2.y;
                if (MODE == 0) {
                    const int bb  = row / NQ;
                    const int pos = row - bb * NQ;
                    float2* dst = reinterpret_cast<float2*>(
                        g_vt + ((size_t)(bb * NH + (cb >> 5)) * NQ + pos) * DH + (cb & 31));
                    *dst = make_float2(v0, v1);
                } else if (MODE == 1) {
                    *reinterpret_cast<float2*>(g_P + (size_t)row * NFUSED + cb)
                        = make_float2(v0, v1);
                } else {
                    const float2 q2 = *reinterpret_cast<const float2*>(
                        addin + (size_t)row * D + cb);
                    *reinterpret_cast<float2*>(Cout + (size_t)row * D + cb)
                        = make_float2(v0 + q2.x, v1 + q2.y);
                }
            }
        }
    }
}

// ---------------- fused softmax + coords + bilinear gather ----------------
// Stage 1: lane i<16 owns point i -> softmax + clamped corner offsets with
// validity folded into weights -> smem table (4 x (offset, weight) per point).
// Stage 2: branch-free. 4 point-groups of 8 lanes; per level: 2 LDS.128 of
// params + 4 unconditional LDG.128 + 16 FFMA. Final xor-reduction over groups.
__global__ __launch_bounds__(256)
void sample_kernel(const float* __restrict__ refp) {
    __shared__ float2 tbl[8][16][4];       // [warp][point][corner] = (offset, weight)
    const int wid   = threadIdx.x >> 5;
    const int gwarp = blockIdx.x * 8 + wid;
    const int lane  = threadIdx.x & 31;
    if (gwarp >= MR * NH) return;
    const int h  = gwarp & 7;
    const int bq = gwarp >> 3;
    const int b  = (bq >= NQ);

    const float* Prow = g_P + (size_t)bq * NFUSED;
    const int i  = lane & 15;          // point index (lanes 16-31 mirror)
    const int il = i >> 2;

    // softmax over the 16 logits of this head
    float lg = Prow[256 + h * 16 + i];
    float mx = lg;
    #pragma unroll
    for (int off = 8; off; off >>= 1)
        mx = fmaxf(mx, __shfl_xor_sync(0xffffffffu, mx, off));
    float e = __expf(lg - mx);
    float ssum = e;
    #pragma unroll
    for (int off = 8; off; off >>= 1)
        ssum += __shfl_xor_sync(0xffffffffu, ssum, off);
    const float wgt = e / ssum;

    // pixel coords + clamped corner table for this lane's point
    {
        const float2 off2 = *reinterpret_cast<const float2*>(Prow + h * 32 + i * 2);
        const float2 ref2 = *reinterpret_cast<const float2*>(refp + (size_t)bq * 8 + il * 2);
        const int Wl = c_LW[il], Hl = c_LH[il], st = c_LS[il];
        const float px = ref2.x * (float)Wl + off2.x - 0.5f;
        const float py = ref2.y * (float)Hl + off2.y - 0.5f;

        const float xf = floorf(px), yf = floorf(py);
        const int   x0 = (int)xf,    y0 = (int)yf;
        const int   x1 = x0 + 1,     y1 = y0 + 1;
        const float wx1 = px - xf,   wy1 = py - yf;
        const float wx0 = 1.f - wx1, wy0 = 1.f - wy1;
        const float vx0 = ((unsigned)x0 < (unsigned)Wl) ? 1.f : 0.f;
        const float vx1 = ((unsigned)x1 < (unsigned)Wl) ? 1.f : 0.f;
        const float vy0 = ((unsigned)y0 < (unsigned)Hl) ? 1.f : 0.f;
        const float vy1 = ((unsigned)y1 < (unsigned)Hl) ? 1.f : 0.f;
        const int cx0 = min(max(x0, 0), Wl - 1);
        const int cx1 = min(max(x1, 0), Wl - 1);
        const int cy0 = min(max(y0, 0), Hl - 1);
        const int cy1 = min(max(y1, 0), Hl - 1);
        const int r0 = st + cy0 * Wl;
        const int r1 = st + cy1 * Wl;
        if (lane < 16) {
            tbl[wid][i][0] = make_float2(__int_as_float((r0 + cx0) * DH), wgt * wy0 * wx0 * vy0 * vx0);
            tbl[wid][i][1] = make_float2(__int_as_float((r0 + cx1) * DH), wgt * wy0 * wx1 * vy0 * vx1);
            tbl[wid][i][2] = make_float2(__int_as_float((r1 + cx0) * DH), wgt * wy1 * wx0 * vy1 * vx0);
            tbl[wid][i][3] = make_float2(__int_as_float((r1 + cx1) * DH), wgt * wy1 * wx1 * vy1 * vx1);
        }
    }
    __syncwarp();

    const int pgrp = lane >> 3;
    const int cq   = (lane & 7) * 4;
    const float* vb = g_vt + ((size_t)(b * NH + h) * NQ) * DH + cq;

    float4 acc = make_float4(0.f, 0.f, 0.f, 0.f);
    #pragma unroll
    for (int j = 0; j < 4; ++j) {      // j = level
        const int p = j * 4 + pgrp;
        const float4 t0 = *reinterpret_cast<const float4*>(&tbl[wid][p][0]); // E00,w00,E01,w01
        const float4 t1 = *reinterpret_cast<const float4*>(&tbl[wid][p][2]); // E10,w10,E11,w11
        const float4 v00 = *reinterpret_cast<const float4*>(vb + __float_as_int(t0.x));
        const float4 v01 = *reinterpret_cast<const float4*>(vb + __float_as_int(t0.z));
        const float4 v10 = *reinterpret_cast<const float4*>(vb + __float_as_int(t1.x));
        const float4 v11 = *reinterpret_cast<const float4*>(vb + __float_as_int(t1.z));
        acc.x += t0.y * v00.x + t0.w * v01.x + t1.y * v10.x + t1.w * v11.x;
        acc.y += t0.y * v00.y + t0.w * v01.y + t1.y * v10.y + t1.w * v11.y;
        acc.z += t0.y * v00.z + t0.w * v01.z + t1.y * v10.z + t1.w * v11.z;
        acc.w += t0.y * v00.w + t0.w * v01.w + t1.y * v10.w + t1.w * v11.w;
    }

    // reduce across the 4 point-groups (lanes xor 8, 16)
    #pragma unroll
    for (int off = 8; off <= 16; off <<= 1) {
        acc.x += __shfl_xor_sync(0xffffffffu, acc.x, off);
        acc.y += __shfl_xor_sync(0xffffffffu, acc.y, off);
        acc.z += __shfl_xor_sync(0xffffffffu, acc.z, off);
        acc.w += __shfl_xor_sync(0xffffffffu, acc.w, off);
    }
    if (lane < 8)
        *reinterpret_cast<float4*>(g_tmp + (size_t)bq * D + h * DH + cq) = acc;
}

// ---------------- launch ----------------
extern "C" void kernel_launch(void* const* d_in, const int* in_sizes, int n_in,
                              void* d_out, int out_size) {
    const float* query = (const float*)d_in[0];
    const float* value = (const float*)d_in[1];
    const float* refp  = (const float*)d_in[2];
    const float* Wv   = (const float*)d_in[5];
    const float* bv   = (const float*)d_in[6];
    const float* Wo   = (const float*)d_in[7];
    const float* bo   = (const float*)d_in[8];
    const float* Wa   = (const float*)d_in[9];
    const float* ba   = (const float*)d_in[10];
    const float* Wout = (const float*)d_in[11];
    const float* bout = (const float*)d_in[12];
    float* out = (float*)d_out;

    pack_w_kernel<<<(D * NFUSED + 255) / 256, 256>>>(Wo, bo, Wa, ba);

    gemm_tc<0><<<dim3(MR / 128, 256 / 128), 256>>>(value, Wv, bv, nullptr, nullptr, 256);
    gemm_tc<1><<<dim3(MR / 128, NFUSED / 128), 256>>>(query, nullptr, nullptr, nullptr, nullptr, NFUSED);

    sample_kernel<<<MR * NH / 8, 256>>>(refp);

    gemm_tc<2><<<dim3(MR / 128, 256 / 128), 256>>>(nullptr, Wout, bout, query, out, 256);
}